// round 14
// baseline (speedup 1.0000x reference)
#include <cuda_runtime.h>
#include <cuda_fp16.h>
#include <cstdint>

// ---------------- problem constants ----------------
#define TOK_LABEL   2
#define ACT_START   5
#define TIME_START  69
#define NB          8
#define NT_SEQ      2048
#define ND          1024
#define N_ACT       64
#define N_TIME      32
#define N_COLS      96
#define M_TOT       (NB * NT_SEQ)
#define ACT_ELEMS   ((size_t)M_TOT * N_ACT)

// GEMM tiling: 128-thread CTAs, 4 warps, warp tile m32 x n48
#define BM       64
#define BK       32
#define NTILES   (ND / BK)       // 32
#define ASTR     40              // smem row stride in halves (80B rows)
#define BSTR     40
#define GEMM_TILES (M_TOT / BM)  // 256
#define SIM_PER_B  5
#define NSIM       (NB * SIM_PER_B)   // 40; grid 296 = 2 x 148 SMs

// ---------------- scratch ----------------
__device__ __align__(16) __half g_Bh[N_COLS * ND];   // folded weights, fp16
__device__ int   g_qlist[NB][NT_SEQ];
__device__ int   g_klist[NB][NT_SEQ];
__device__ int   g_kcls [NB][NT_SEQ];
__device__ int   g_qcnt[NB];
__device__ int   g_kcnt[NB];
__device__ float g_krn[NB][NT_SEQ];                  // 1/||h_k|| indexed by POSITION
__device__ int   g_tile_ctr;                         // work-stealing m-tile counter

// ---------------- helpers ----------------
__device__ __forceinline__ float softplus_f(float x) {
    return (x > 20.0f) ? x : log1pf(expf(x));
}
__device__ __forceinline__ uint32_t smem_u32(const void* p) {
    uint32_t a;
    asm("{ .reg .u64 t; cvta.to.shared.u64 t, %1; cvt.u32.u64 %0, t; }" : "=r"(a) : "l"(p));
    return a;
}
__device__ __forceinline__ void ldsm4(uint32_t* r, uint32_t addr) {
    asm volatile("ldmatrix.sync.aligned.m8n8.x4.shared.b16 {%0,%1,%2,%3}, [%4];"
                 : "=r"(r[0]), "=r"(r[1]), "=r"(r[2]), "=r"(r[3]) : "r"(addr));
}
__device__ __forceinline__ void mma_f16(float* c, const uint32_t* a, const uint32_t* b) {
    asm volatile(
        "mma.sync.aligned.m16n8k16.row.col.f32.f16.f16.f32 "
        "{%0,%1,%2,%3}, {%4,%5,%6,%7}, {%8,%9}, {%0,%1,%2,%3};"
        : "+f"(c[0]), "+f"(c[1]), "+f"(c[2]), "+f"(c[3])
        : "r"(a[0]), "r"(a[1]), "r"(a[2]), "r"(a[3]), "r"(b[0]), "r"(b[1]));
}
__device__ __forceinline__ void cp_async16(uint32_t dst, const void* src) {
    asm volatile("cp.async.ca.shared.global [%0], [%1], 16;" :: "r"(dst), "l"(src));
}
__device__ __forceinline__ void cp_commit() {
    asm volatile("cp.async.commit_group;" ::: "memory");
}
__device__ __forceinline__ void cp_wait0() {
    asm volatile("cp.async.wait_group 0;" ::: "memory");
}
__device__ __forceinline__ void cp_wait1() {
    asm volatile("cp.async.wait_group 1;" ::: "memory");
}
// convert 16 fp32 -> 16 fp16 packed into 2 uint4
__device__ __forceinline__ void cvt16(const float4* f, uint4& o0, uint4& o1) {
    uint32_t u[8];
    #pragma unroll
    for (int i = 0; i < 4; i++) {
        __half2 a = __float22half2_rn(make_float2(f[i].x, f[i].y));
        __half2 b = __float22half2_rn(make_float2(f[i].z, f[i].w));
        u[2 * i]     = *(uint32_t*)&a;
        u[2 * i + 1] = *(uint32_t*)&b;
    }
    o0 = make_uint4(u[0], u[1], u[2], u[3]);
    o1 = make_uint4(u[4], u[5], u[6], u[7]);
}

// ---------------- kernel 1: fold + scan/zero + parallel key norms ----------------
#define WC_BLOCKS   96      // fold: 96 blocks x 1024 elems
#define SCAN_BLOCKS NB      // 8
#define NORM_SEGS   4       // 4 norm blocks per batch (512 positions each)
#define NORM_BLOCKS (NB * NORM_SEGS)

__global__ void prep_kernel(const float* __restrict__ E,
                            const float* __restrict__ Wn,
                            const float* __restrict__ Wt,
                            const float* __restrict__ tsa, const float* __restrict__ tst,
                            const int* __restrict__ tokens,
                            const float* __restrict__ h,
                            float* __restrict__ out) {
    const int tid = threadIdx.x;
    if (blockIdx.x < WC_BLOCKS) {
        if (blockIdx.x == 0 && tid == 0) g_tile_ctr = 0;   // reset work-stealing ctr
        int i4 = (blockIdx.x * blockDim.x + tid) * 4;
        float sa = softplus_f(*tsa);
        float st = softplus_f(*tst);
        int r = i4 >> 10;
        int c = i4 & (ND - 1);
        float4 w, e;
        float s;
        if (r < N_ACT) {
            w = *(const float4*)(Wn + r * ND + c);
            e = *(const float4*)(E + (ACT_START + r) * ND + c);
            s = sa;
        } else {
            w = *(const float4*)(Wt + (r - N_ACT) * ND + c);
            e = *(const float4*)(E + (TIME_START + (r - N_ACT)) * ND + c);
            s = st;
        }
        __half2 p0 = __float22half2_rn(make_float2(w.x + s * e.x, w.y + s * e.y));
        __half2 p1 = __float22half2_rn(make_float2(w.z + s * e.z, w.w + s * e.w));
        uint2 o = make_uint2(*(uint32_t*)&p0, *(uint32_t*)&p1);
        *(uint2*)(g_Bh + i4) = o;
        return;
    }
    if (blockIdx.x < WC_BLOCKS + SCAN_BLOCKS) {
        // scan + zero label-query output rows: one block per batch
        const int b   = blockIdx.x - WC_BLOCKS;
        const int* tk = tokens + b * NT_SEQ;
        if (tid == 0) { g_qcnt[b] = 0; g_kcnt[b] = 0; }
        __syncthreads();
        #pragma unroll
        for (int r = 0; r < NT_SEQ / 256; r++) {
            int pos = tid + r * 256;
            int tok = tk[pos];
            if (tok == TOK_LABEL) {
                int s = atomicAdd(&g_qcnt[b], 1);
                g_qlist[b][s] = pos;
            }
            if (pos >= 1 && tok >= ACT_START && tk[pos - 1] == TOK_LABEL) {
                int s = atomicAdd(&g_kcnt[b], 1);
                g_klist[b][s] = pos;
                g_kcls[b][s]  = (tok < TIME_START) ? (tok - ACT_START)
                                                   : (N_ACT + (tok - TIME_START));
            }
        }
        __syncthreads();
        const int qc = g_qcnt[b];
        float* out_time = out + ACT_ELEMS;
        for (int idx = tid; idx < qc * N_COLS; idx += 256) {
            int qi  = idx / N_COLS;
            int col = idx - qi * N_COLS;
            size_t m = (size_t)b * NT_SEQ + g_qlist[b][qi];
            if (col < N_ACT) out[m * N_ACT + col] = 0.0f;
            else             out_time[m * N_TIME + (col - N_ACT)] = 0.0f;
        }
        return;
    }
    // norm blocks: 1/||h_k|| for all key positions, independent of the scan
    const int nb   = blockIdx.x - WC_BLOCKS - SCAN_BLOCKS;
    const int b    = nb >> 2;
    const int seg  = nb & (NORM_SEGS - 1);
    const int warp = tid >> 5;
    const int lane = tid & 31;
    const int* tk  = tokens + b * NT_SEQ;
    const float* hb = h + (size_t)b * NT_SEQ * ND;

    const int base = seg * (NT_SEQ / NORM_SEGS) + warp * 64;   // 8 warps x 64 positions
    #pragma unroll
    for (int ch = 0; ch < 2; ch++) {
        int pos = base + ch * 32 + lane;
        bool hit = (pos >= 1) && (tk[pos] >= ACT_START) && (tk[pos - 1] == TOK_LABEL);
        unsigned mask = __ballot_sync(0xffffffffu, hit);
        while (mask) {
            int bit = __ffs(mask) - 1;
            mask &= mask - 1;
            int kp = base + ch * 32 + bit;
            const float* row = hb + (size_t)kp * ND;
            float s = 0.0f;
            #pragma unroll
            for (int c = 0; c < 8; c++) {
                float4 v = *(const float4*)(row + c * 128 + lane * 4);
                s += v.x*v.x + v.y*v.y + v.z*v.z + v.w*v.w;
            }
            #pragma unroll
            for (int o = 16; o; o >>= 1) s += __shfl_xor_sync(0xffffffffu, s, o);
            if (lane == 0) g_krn[b][kp] = 1.0f / fmaxf(sqrtf(s), 1e-12f);
        }
    }
}

// ---------------- kernel 2: sims (blocks 0..39) + fp16 GEMM, deep A+B pipelines ----------------
__global__ __launch_bounds__(128, 2)
void gemm_kernel(const float* __restrict__ h, float* __restrict__ out,
                 const float* __restrict__ bn, const float* __restrict__ bt,
                 const float* __restrict__ cta, const float* __restrict__ ctt,
                 const float* __restrict__ csa, const float* __restrict__ cst,
                 const int* __restrict__ tokens) {
    __shared__ __align__(16) __half sA[2][BM * ASTR];       // 2 x 5120 B
    __shared__ __align__(16) __half sB[3][N_COLS * BSTR];   // 3 x 7680 B
    __shared__ float s_bias[N_COLS];
    __shared__ int   s_tile;

    const int tid  = threadIdx.x;
    const int warp = tid >> 5;
    const int lane = tid & 31;
    float* out_time = out + ACT_ELEMS;

    // ================= sim path (blocks 0..NSIM-1) =================
    if (blockIdx.x < NSIM) {
        const int sid   = blockIdx.x;
        const int b     = sid / SIM_PER_B;
        const int qslot = sid - b * SIM_PER_B;
        const int qcnt  = g_qcnt[b];
        if (qslot >= qcnt) return;
        const int kc    = g_kcnt[b];
        const float tau_a = softplus_f(*cta);
        const float tau_t = softplus_f(*ctt);
        const float sca   = softplus_f(*csa);
        const float sct   = softplus_f(*cst);
        const float* hb   = h + (size_t)b * NT_SEQ * ND;
        float* s_acc = s_bias;

        for (int qi = qslot; qi < qcnt; qi += SIM_PER_B) {
            __syncthreads();
            if (tid < N_COLS) s_acc[tid] = 0.0f;
            const int q = g_qlist[b][qi];
            const float* hq = hb + (size_t)q * ND;
            float4 qv[8];
            float nq = 0.0f;
            #pragma unroll
            for (int c = 0; c < 8; c++) {
                qv[c] = *(const float4*)(hq + c * 128 + lane * 4);
                nq += qv[c].x*qv[c].x + qv[c].y*qv[c].y + qv[c].z*qv[c].z + qv[c].w*qv[c].w;
            }
            #pragma unroll
            for (int o = 16; o; o >>= 1) nq += __shfl_xor_sync(0xffffffffu, nq, o);
            const float rnq = 1.0f / fmaxf(sqrtf(nq), 1e-12f);
            __syncthreads();

            // 4 warps, 2 keys per warp per round
            for (int j = warp; j < kc; j += 8) {
                const int jb = j + 4;
                const bool h2 = jb < kc;
                int k1 = g_klist[b][j];
                int k2 = h2 ? g_klist[b][jb] : k1;
                bool m1 = (k1 < q);
                bool m2 = h2 && (k2 < q);
                if (!m1 && !m2) continue;
                const float* p1 = hb + (size_t)k1 * ND;
                const float* p2 = hb + (size_t)k2 * ND;
                float d1 = 0.0f, d2 = 0.0f;
                #pragma unroll
                for (int c = 0; c < 8; c++) {
                    float4 a = *(const float4*)(p1 + c * 128 + lane * 4);
                    float4 v = *(const float4*)(p2 + c * 128 + lane * 4);
                    d1 += qv[c].x*a.x + qv[c].y*a.y + qv[c].z*a.z + qv[c].w*a.w;
                    d2 += qv[c].x*v.x + qv[c].y*v.y + qv[c].z*v.z + qv[c].w*v.w;
                }
                #pragma unroll
                for (int o = 16; o; o >>= 1) {
                    d1 += __shfl_xor_sync(0xffffffffu, d1, o);
                    d2 += __shfl_xor_sync(0xffffffffu, d2, o);
                }
                if (lane == 0) {
                    if (m1) {
                        int cls = g_kcls[b][j];
                        float sim = d1 * rnq * g_krn[b][k1];
                        atomicAdd(&s_acc[cls], sim * (cls < N_ACT ? tau_a : tau_t));
                    }
                    if (m2) {
                        int cls = g_kcls[b][jb];
                        float sim = d2 * rnq * g_krn[b][k2];
                        atomicAdd(&s_acc[cls], sim * (cls < N_ACT ? tau_a : tau_t));
                    }
                }
            }
            __syncthreads();
            const size_t m = (size_t)b * NT_SEQ + q;
            if (tid < N_ACT)
                atomicAdd(&out[m * N_ACT + tid], sca * s_acc[tid]);
            else if (tid < N_COLS)
                atomicAdd(&out_time[m * N_TIME + (tid - N_ACT)], sct * s_acc[tid]);
        }
        return;
    }

    // ================= gemm path: work-stealing over 256 m-tiles =================
    if (tid < N_COLS) s_bias[tid] = (tid < N_ACT) ? bn[tid] : bt[tid - N_ACT];

    const int wm = warp & 1;       // m-tile of 32
    const int wn = warp >> 1;      // n-tile of 48

    // A load coords: 2 threads per row, 16 floats each (BK=32)
    const int aRow = tid >> 1;
    const int aKh  = (tid & 1) * 16;
    const uint32_t uA0 = smem_u32(&sA[0][0]);
    const uint32_t uA1 = smem_u32(&sA[1][0]);
    const uint32_t uB[3] = { smem_u32(&sB[0][0]), smem_u32(&sB[1][0]), smem_u32(&sB[2][0]) };
    const uint32_t aoff0 = (uint32_t)(((wm * 32 +      (lane & 15)) * ASTR + (lane >> 4) * 8) * 2);
    const uint32_t aoff1 = (uint32_t)(((wm * 32 + 16 + (lane & 15)) * ASTR + (lane >> 4) * 8) * 2);

    // per-thread B cp.async coordinates (3 chunks of 16B)
    int bRow[3], bPart[3];
    #pragma unroll
    for (int i = 0; i < 3; i++) { int c = tid + 128 * i; bRow[i] = c >> 2; bPart[i] = c & 3; }

    for (;;) {
        if (tid == 0) s_tile = atomicAdd(&g_tile_ctr, 1);
        __syncthreads();
        const int tileIdx = s_tile;
        if (tileIdx >= GEMM_TILES) break;
        const int m0 = tileIdx * BM;

        const float* gA = h + (size_t)(m0 + aRow) * ND + aKh;

        float acc[2][6][4];
        #pragma unroll
        for (int i = 0; i < 2; i++)
            #pragma unroll
            for (int j = 0; j < 6; j++)
                #pragma unroll
                for (int c = 0; c < 4; c++) acc[i][j][c] = 0.0f;

        float4 fa[2][4];   // double-buffered A prefetch registers (distance-2)

        // ---- prologue: issue B(0),B(1); LDG A(0),A(1); store A(0); wait B(0) ----
        #pragma unroll
        for (int i = 0; i < 3; i++)
            cp_async16(uB[0] + (uint32_t)(bRow[i] * (BSTR * 2) + bPart[i] * 16),
                       (const char*)g_Bh + (size_t)bRow[i] * (ND * 2) + bPart[i] * 16);
        cp_commit();
        #pragma unroll
        for (int i = 0; i < 3; i++)
            cp_async16(uB[1] + (uint32_t)(bRow[i] * (BSTR * 2) + bPart[i] * 16),
                       (const char*)g_Bh + (size_t)bRow[i] * (ND * 2) + BK * 2 + bPart[i] * 16);
        cp_commit();
        #pragma unroll
        for (int i = 0; i < 4; i++) fa[0][i] = *(const float4*)(gA + 4 * i);
        #pragma unroll
        for (int i = 0; i < 4; i++) fa[1][i] = *(const float4*)(gA + BK + 4 * i);
        {
            uint4 o0, o1; cvt16(fa[0], o0, o1);
            __half* dA = &sA[0][aRow * ASTR + aKh];
            *(uint4*)dA = o0; *(uint4*)(dA + 8) = o1;
        }
        cp_wait1();            // B(0) complete; B(1) may still fly
        __syncthreads();

        int curB = 0;
        for (int t = 0; t < NTILES; t++) {
            const int curA = t & 1;

            // ---- store A(t+1) (LDG issued >=1 iteration ago -> latency hidden) ----
            if (t + 1 < NTILES) {
                uint4 o0, o1; cvt16(fa[curA ^ 1], o0, o1);
                __half* dA = &sA[curA ^ 1][aRow * ASTR + aKh];
                *(uint4*)dA = o0; *(uint4*)(dA + 8) = o1;
            }
            // ---- issue LDG A(t+2) into the register set just freed (fa[t&1]) ----
            if (t + 2 < NTILES) {
                const float* a2 = gA + (t + 2) * BK;
                #pragma unroll
                for (int i = 0; i < 4; i++) fa[curA][i] = *(const float4*)(a2 + 4 * i);
            }
            // ---- issue B(t+2) ----
            if (t + 2 < NTILES) {
                int dst = curB + 2; if (dst >= 3) dst -= 3;
                #pragma unroll
                for (int i = 0; i < 3; i++)
                    cp_async16(uB[dst] + (uint32_t)(bRow[i] * (BSTR * 2) + bPart[i] * 16),
                               (const char*)g_Bh + (size_t)bRow[i] * (ND * 2) + (t + 2) * (BK * 2) + bPart[i] * 16);
                cp_commit();
            }

            // ---- compute tile t ----
            const uint32_t uA = curA ? uA1 : uA0;
            const __half* sb = &sB[curB][0];
            #pragma unroll
            for (int ks = 0; ks < 2; ks++) {
                uint32_t a0[4], a1[4];
                ldsm4(a0, uA + aoff0 + ks * 32);
                ldsm4(a1, uA + aoff1 + ks * 32);
                uint32_t b[6][2];
                #pragma unroll
                for (int j = 0; j < 6; j++) {
                    int n = wn * 48 + j * 8 + (lane >> 2);
                    const __half* p = sb + n * BSTR + ks * 16 + (lane & 3) * 2;
                    b[j][0] = *(const uint32_t*)p;
                    b[j][1] = *(const uint32_t*)(p + 8);
                }
                #pragma unroll
                for (int j = 0; j < 6; j++) {
                    mma_f16(acc[0][j], a0, b[j]);
                    mma_f16(acc[1][j], a1, b[j]);
                }
            }

            // ---- wait: B(t+1) ready (issued one iteration ago) ----
            if (t + 2 < NTILES)      cp_wait1();
            else if (t + 1 < NTILES) cp_wait0();
            __syncthreads();

            curB++; if (curB == 3) curB = 0;
        }

        // ---- epilogue: plain stores; atomicAdd into pre-zeroed label rows ----
        #pragma unroll
        for (int mt = 0; mt < 2; mt++) {
            size_t r0 = (size_t)m0 + wm * 32 + mt * 16 + (lane >> 2);
            size_t r1 = r0 + 8;
            const bool l0 = (tokens[r0] == TOK_LABEL);
            const bool l1 = (tokens[r1] == TOK_LABEL);
            #pragma unroll
            for (int j = 0; j < 6; j++) {
                int c0 = wn * 48 + j * 8 + (lane & 3) * 2;
                float b0 = s_bias[c0], b1 = s_bias[c0 + 1];
                float2 v0 = make_float2(acc[mt][j][0] + b0, acc[mt][j][1] + b1);
                float2 v1 = make_float2(acc[mt][j][2] + b0, acc[mt][j][3] + b1);
                float* p0;
                float* p1;
                if (c0 < N_ACT) {
                    p0 = out + r0 * N_ACT + c0;
                    p1 = out + r1 * N_ACT + c0;
                } else {
                    p0 = out_time + r0 * N_TIME + (c0 - N_ACT);
                    p1 = out_time + r1 * N_TIME + (c0 - N_ACT);
                }
                if (l0) { atomicAdd(p0, v0.x); atomicAdd(p0 + 1, v0.y); }
                else    { *(float2*)p0 = v0; }
                if (l1) { atomicAdd(p1, v1.x); atomicAdd(p1 + 1, v1.y); }
                else    { *(float2*)p1 = v1; }
            }
        }
        __syncthreads();   // all reads of smem stages done before next m-tile
    }
}

// ---------------- launch ----------------
extern "C" void kernel_launch(void* const* d_in, const int* in_sizes, int n_in,
                              void* d_out, int out_size) {
    const int*   tokens = (const int*)  d_in[0];
    const float* h      = (const float*)d_in[1];
    const float* E      = (const float*)d_in[2];
    const float* Wn     = (const float*)d_in[3];
    const float* bn     = (const float*)d_in[4];
    const float* Wt     = (const float*)d_in[5];
    const float* bt     = (const float*)d_in[6];
    const float* tsa    = (const float*)d_in[7];
    const float* tst    = (const float*)d_in[8];
    const float* csa    = (const float*)d_in[9];
    const float* cst    = (const float*)d_in[10];
    const float* cta    = (const float*)d_in[11];
    const float* ctt    = (const float*)d_in[12];
    float* out = (float*)d_out;

    prep_kernel<<<WC_BLOCKS + SCAN_BLOCKS + NORM_BLOCKS, 256>>>(E, Wn, Wt, tsa, tst, tokens, h, out);
    gemm_kernel<<<NSIM + GEMM_TILES, 128>>>(h, out, bn, bt, cta, ctt, csa, cst, tokens);
}

// round 15
// speedup vs baseline: 1.4400x; 1.4400x over previous
#include <cuda_runtime.h>
#include <cuda_fp16.h>
#include <cstdint>

// ---------------- problem constants ----------------
#define TOK_LABEL   2
#define ACT_START   5
#define TIME_START  69
#define NB          8
#define NT_SEQ      2048
#define ND          1024
#define N_ACT       64
#define N_TIME      32
#define N_COLS      96
#define M_TOT       (NB * NT_SEQ)
#define ACT_ELEMS   ((size_t)M_TOT * N_ACT)

// GEMM tiling: 128-thread CTAs, 4 warps, warp tile m32 x n48
#define BM       64
#define BK       32
#define NTILES   (ND / BK)       // 32 (even; loop unrolled by 2)
#define ASTR     40              // smem row stride in halves (80B rows)
#define BSTR     40
#define GEMM_TILES (M_TOT / BM)  // 256
#define SIM_PER_B  5
#define NSIM       (NB * SIM_PER_B)   // 40; grid 296 = 2 x 148 SMs

// ---------------- scratch ----------------
__device__ __align__(16) __half g_Bh[N_COLS * ND];   // folded weights, fp16
__device__ int   g_qlist[NB][NT_SEQ];
__device__ int   g_klist[NB][NT_SEQ];
__device__ int   g_kcls [NB][NT_SEQ];
__device__ int   g_qcnt[NB];
__device__ int   g_kcnt[NB];
__device__ float g_krn[NB][NT_SEQ];                  // 1/||h_k|| indexed by POSITION

// ---------------- helpers ----------------
__device__ __forceinline__ float softplus_f(float x) {
    return (x > 20.0f) ? x : log1pf(expf(x));
}
__device__ __forceinline__ uint32_t smem_u32(const void* p) {
    uint32_t a;
    asm("{ .reg .u64 t; cvta.to.shared.u64 t, %1; cvt.u32.u64 %0, t; }" : "=r"(a) : "l"(p));
    return a;
}
__device__ __forceinline__ void ldsm4(uint32_t* r, uint32_t addr) {
    asm volatile("ldmatrix.sync.aligned.m8n8.x4.shared.b16 {%0,%1,%2,%3}, [%4];"
                 : "=r"(r[0]), "=r"(r[1]), "=r"(r[2]), "=r"(r[3]) : "r"(addr));
}
__device__ __forceinline__ void mma_f16(float* c, const uint32_t* a, const uint32_t* b) {
    asm volatile(
        "mma.sync.aligned.m16n8k16.row.col.f32.f16.f16.f32 "
        "{%0,%1,%2,%3}, {%4,%5,%6,%7}, {%8,%9}, {%0,%1,%2,%3};"
        : "+f"(c[0]), "+f"(c[1]), "+f"(c[2]), "+f"(c[3])
        : "r"(a[0]), "r"(a[1]), "r"(a[2]), "r"(a[3]), "r"(b[0]), "r"(b[1]));
}
__device__ __forceinline__ void cp_async16(uint32_t dst, const void* src) {
    asm volatile("cp.async.ca.shared.global [%0], [%1], 16;" :: "r"(dst), "l"(src));
}
__device__ __forceinline__ void cp_commit() {
    asm volatile("cp.async.commit_group;" ::: "memory");
}
__device__ __forceinline__ void cp_wait0() {
    asm volatile("cp.async.wait_group 0;" ::: "memory");
}
// convert 16 fp32 -> 16 fp16 packed into 2 uint4
__device__ __forceinline__ void cvt16(const float4* f, uint4& o0, uint4& o1) {
    uint32_t u[8];
    #pragma unroll
    for (int i = 0; i < 4; i++) {
        __half2 a = __float22half2_rn(make_float2(f[i].x, f[i].y));
        __half2 b = __float22half2_rn(make_float2(f[i].z, f[i].w));
        u[2 * i]     = *(uint32_t*)&a;
        u[2 * i + 1] = *(uint32_t*)&b;
    }
    o0 = make_uint4(u[0], u[1], u[2], u[3]);
    o1 = make_uint4(u[4], u[5], u[6], u[7]);
}

// ---------------- kernel 1: fold + scan/zero + parallel key norms ----------------
#define WC_BLOCKS   96      // fold: 96 blocks x 1024 elems
#define SCAN_BLOCKS NB      // 8
#define NORM_SEGS   4       // 4 norm blocks per batch (512 positions each)
#define NORM_BLOCKS (NB * NORM_SEGS)

__global__ void prep_kernel(const float* __restrict__ E,
                            const float* __restrict__ Wn,
                            const float* __restrict__ Wt,
                            const float* __restrict__ tsa, const float* __restrict__ tst,
                            const int* __restrict__ tokens,
                            const float* __restrict__ h,
                            float* __restrict__ out) {
    const int tid = threadIdx.x;
    if (blockIdx.x < WC_BLOCKS) {
        int i4 = (blockIdx.x * blockDim.x + tid) * 4;
        float sa = softplus_f(*tsa);
        float st = softplus_f(*tst);
        int r = i4 >> 10;
        int c = i4 & (ND - 1);
        float4 w, e;
        float s;
        if (r < N_ACT) {
            w = *(const float4*)(Wn + r * ND + c);
            e = *(const float4*)(E + (ACT_START + r) * ND + c);
            s = sa;
        } else {
            w = *(const float4*)(Wt + (r - N_ACT) * ND + c);
            e = *(const float4*)(E + (TIME_START + (r - N_ACT)) * ND + c);
            s = st;
        }
        __half2 p0 = __float22half2_rn(make_float2(w.x + s * e.x, w.y + s * e.y));
        __half2 p1 = __float22half2_rn(make_float2(w.z + s * e.z, w.w + s * e.w));
        uint2 o = make_uint2(*(uint32_t*)&p0, *(uint32_t*)&p1);
        *(uint2*)(g_Bh + i4) = o;
        return;
    }
    if (blockIdx.x < WC_BLOCKS + SCAN_BLOCKS) {
        // scan + zero label-query output rows: one block per batch
        const int b   = blockIdx.x - WC_BLOCKS;
        const int* tk = tokens + b * NT_SEQ;
        if (tid == 0) { g_qcnt[b] = 0; g_kcnt[b] = 0; }
        __syncthreads();
        #pragma unroll
        for (int r = 0; r < NT_SEQ / 256; r++) {
            int pos = tid + r * 256;
            int tok = tk[pos];
            if (tok == TOK_LABEL) {
                int s = atomicAdd(&g_qcnt[b], 1);
                g_qlist[b][s] = pos;
            }
            if (pos >= 1 && tok >= ACT_START && tk[pos - 1] == TOK_LABEL) {
                int s = atomicAdd(&g_kcnt[b], 1);
                g_klist[b][s] = pos;
                g_kcls[b][s]  = (tok < TIME_START) ? (tok - ACT_START)
                                                   : (N_ACT + (tok - TIME_START));
            }
        }
        __syncthreads();
        const int qc = g_qcnt[b];
        float* out_time = out + ACT_ELEMS;
        for (int idx = tid; idx < qc * N_COLS; idx += 256) {
            int qi  = idx / N_COLS;
            int col = idx - qi * N_COLS;
            size_t m = (size_t)b * NT_SEQ + g_qlist[b][qi];
            if (col < N_ACT) out[m * N_ACT + col] = 0.0f;
            else             out_time[m * N_TIME + (col - N_ACT)] = 0.0f;
        }
        return;
    }
    // norm blocks: 1/||h_k|| for all key positions, independent of the scan
    const int nb   = blockIdx.x - WC_BLOCKS - SCAN_BLOCKS;
    const int b    = nb >> 2;
    const int seg  = nb & (NORM_SEGS - 1);
    const int warp = tid >> 5;
    const int lane = tid & 31;
    const int* tk  = tokens + b * NT_SEQ;
    const float* hb = h + (size_t)b * NT_SEQ * ND;

    const int base = seg * (NT_SEQ / NORM_SEGS) + warp * 64;   // 8 warps x 64 positions
    #pragma unroll
    for (int ch = 0; ch < 2; ch++) {
        int pos = base + ch * 32 + lane;
        bool hit = (pos >= 1) && (tk[pos] >= ACT_START) && (tk[pos - 1] == TOK_LABEL);
        unsigned mask = __ballot_sync(0xffffffffu, hit);
        while (mask) {
            int bit = __ffs(mask) - 1;
            mask &= mask - 1;
            int kp = base + ch * 32 + bit;
            const float* row = hb + (size_t)kp * ND;
            float s = 0.0f;
            #pragma unroll
            for (int c = 0; c < 8; c++) {
                float4 v = *(const float4*)(row + c * 128 + lane * 4);
                s += v.x*v.x + v.y*v.y + v.z*v.z + v.w*v.w;
            }
            #pragma unroll
            for (int o = 16; o; o >>= 1) s += __shfl_xor_sync(0xffffffffu, s, o);
            if (lane == 0) g_krn[b][kp] = 1.0f / fmaxf(sqrtf(s), 1e-12f);
        }
    }
}

// ---------------- kernel 2: sims (blocks 0..39) + fp16 GEMM (distance-2 A pipeline) ----------------
__global__ __launch_bounds__(128, 2)
void gemm_kernel(const float* __restrict__ h, float* __restrict__ out,
                 const float* __restrict__ bn, const float* __restrict__ bt,
                 const float* __restrict__ cta, const float* __restrict__ ctt,
                 const float* __restrict__ csa, const float* __restrict__ cst,
                 const int* __restrict__ tokens) {
    __shared__ __align__(16) __half sA[2][BM * ASTR];       // 2 x 5120 B
    __shared__ __align__(16) __half sB[2][N_COLS * BSTR];   // 2 x 7680 B
    __shared__ float s_bias[N_COLS];

    const int tid  = threadIdx.x;
    const int warp = tid >> 5;
    const int lane = tid & 31;
    float* out_time = out + ACT_ELEMS;

    // ================= sim path (blocks 0..NSIM-1) =================
    if (blockIdx.x < NSIM) {
        const int sid   = blockIdx.x;
        const int b     = sid / SIM_PER_B;
        const int qslot = sid - b * SIM_PER_B;
        const int qcnt  = g_qcnt[b];
        if (qslot >= qcnt) return;
        const int kc    = g_kcnt[b];
        const float tau_a = softplus_f(*cta);
        const float tau_t = softplus_f(*ctt);
        const float sca   = softplus_f(*csa);
        const float sct   = softplus_f(*cst);
        const float* hb   = h + (size_t)b * NT_SEQ * ND;
        float* s_acc = s_bias;

        for (int qi = qslot; qi < qcnt; qi += SIM_PER_B) {
            __syncthreads();
            if (tid < N_COLS) s_acc[tid] = 0.0f;
            const int q = g_qlist[b][qi];
            const float* hq = hb + (size_t)q * ND;
            float4 qv[8];
            float nq = 0.0f;
            #pragma unroll
            for (int c = 0; c < 8; c++) {
                qv[c] = *(const float4*)(hq + c * 128 + lane * 4);
                nq += qv[c].x*qv[c].x + qv[c].y*qv[c].y + qv[c].z*qv[c].z + qv[c].w*qv[c].w;
            }
            #pragma unroll
            for (int o = 16; o; o >>= 1) nq += __shfl_xor_sync(0xffffffffu, nq, o);
            const float rnq = 1.0f / fmaxf(sqrtf(nq), 1e-12f);
            __syncthreads();

            // 4 warps, 2 keys per warp per round
            for (int j = warp; j < kc; j += 8) {
                const int jb = j + 4;
                const bool h2 = jb < kc;
                int k1 = g_klist[b][j];
                int k2 = h2 ? g_klist[b][jb] : k1;
                bool m1 = (k1 < q);
                bool m2 = h2 && (k2 < q);
                if (!m1 && !m2) continue;
                const float* p1 = hb + (size_t)k1 * ND;
                const float* p2 = hb + (size_t)k2 * ND;
                float d1 = 0.0f, d2 = 0.0f;
                #pragma unroll
                for (int c = 0; c < 8; c++) {
                    float4 a = *(const float4*)(p1 + c * 128 + lane * 4);
                    float4 v = *(const float4*)(p2 + c * 128 + lane * 4);
                    d1 += qv[c].x*a.x + qv[c].y*a.y + qv[c].z*a.z + qv[c].w*a.w;
                    d2 += qv[c].x*v.x + qv[c].y*v.y + qv[c].z*v.z + qv[c].w*v.w;
                }
                #pragma unroll
                for (int o = 16; o; o >>= 1) {
                    d1 += __shfl_xor_sync(0xffffffffu, d1, o);
                    d2 += __shfl_xor_sync(0xffffffffu, d2, o);
                }
                if (lane == 0) {
                    if (m1) {
                        int cls = g_kcls[b][j];
                        float sim = d1 * rnq * g_krn[b][k1];
                        atomicAdd(&s_acc[cls], sim * (cls < N_ACT ? tau_a : tau_t));
                    }
                    if (m2) {
                        int cls = g_kcls[b][jb];
                        float sim = d2 * rnq * g_krn[b][k2];
                        atomicAdd(&s_acc[cls], sim * (cls < N_ACT ? tau_a : tau_t));
                    }
                }
            }
            __syncthreads();
            const size_t m = (size_t)b * NT_SEQ + q;
            if (tid < N_ACT)
                atomicAdd(&out[m * N_ACT + tid], sca * s_acc[tid]);
            else if (tid < N_COLS)
                atomicAdd(&out_time[m * N_TIME + (tid - N_ACT)], sct * s_acc[tid]);
        }
        return;
    }

    // ================= gemm path: one m-tile per CTA, static assignment =================
    if (tid < N_COLS) s_bias[tid] = (tid < N_ACT) ? bn[tid] : bt[tid - N_ACT];

    const int wm = warp & 1;       // m-tile of 32
    const int wn = warp >> 1;      // n-tile of 48
    const int m0 = (blockIdx.x - NSIM) * BM;

    // A load coords: 2 threads per row, 16 floats each (BK=32)
    const int aRow = tid >> 1;
    const int aKh  = (tid & 1) * 16;
    const float* gA = h + (size_t)(m0 + aRow) * ND + aKh;

    const uint32_t uA0 = smem_u32(&sA[0][0]);
    const uint32_t uA1 = smem_u32(&sA[1][0]);
    const uint32_t uB0 = smem_u32(&sB[0][0]);
    const uint32_t uB1 = smem_u32(&sB[1][0]);
    const uint32_t aoff0 = (uint32_t)(((wm * 32 +      (lane & 15)) * ASTR + (lane >> 4) * 8) * 2);
    const uint32_t aoff1 = (uint32_t)(((wm * 32 + 16 + (lane & 15)) * ASTR + (lane >> 4) * 8) * 2);

    // per-thread B cp.async coordinates (3 chunks of 16B)
    int bRow[3], bPart[3];
    #pragma unroll
    for (int i = 0; i < 3; i++) { int c = tid + 128 * i; bRow[i] = c >> 2; bPart[i] = c & 3; }

    float acc[2][6][4];
    #pragma unroll
    for (int i = 0; i < 2; i++)
        #pragma unroll
        for (int j = 0; j < 6; j++)
            #pragma unroll
            for (int c = 0; c < 4; c++) acc[i][j][c] = 0.0f;

    float4 fa0[4], fa1[4];   // named register sets: A(t) lives in fa0 for even t, fa1 for odd t

    // ---- prologue: issue B(0); LDG A(0),A(1); store A(0)->sA0; wait; sync ----
    #pragma unroll
    for (int i = 0; i < 3; i++)
        cp_async16(uB0 + (uint32_t)(bRow[i] * (BSTR * 2) + bPart[i] * 16),
                   (const char*)g_Bh + (size_t)bRow[i] * (ND * 2) + bPart[i] * 16);
    cp_commit();
    #pragma unroll
    for (int i = 0; i < 4; i++) fa0[i] = *(const float4*)(gA + 4 * i);
    #pragma unroll
    for (int i = 0; i < 4; i++) fa1[i] = *(const float4*)(gA + BK + 4 * i);
    {
        uint4 o0, o1; cvt16(fa0, o0, o1);
        __half* dA = &sA[0][aRow * ASTR + aKh];
        *(uint4*)dA = o0; *(uint4*)(dA + 8) = o1;
    }
    cp_wait0();
    __syncthreads();

    // compute macro: tile from (uA, sb) into acc
    #define COMPUTE_TILE(uA, sb)                                                        \
    {                                                                                   \
        _Pragma("unroll")                                                               \
        for (int ks = 0; ks < 2; ks++) {                                                \
            uint32_t a0[4], a1[4];                                                      \
            ldsm4(a0, (uA) + aoff0 + ks * 32);                                          \
            ldsm4(a1, (uA) + aoff1 + ks * 32);                                          \
            uint32_t b[6][2];                                                           \
            _Pragma("unroll")                                                           \
            for (int j = 0; j < 6; j++) {                                               \
                int n = wn * 48 + j * 8 + (lane >> 2);                                  \
                const __half* p = (sb) + n * BSTR + ks * 16 + (lane & 3) * 2;           \
                b[j][0] = *(const uint32_t*)p;                                          \
                b[j][1] = *(const uint32_t*)(p + 8);                                    \
            }                                                                           \
            _Pragma("unroll")                                                           \
            for (int j = 0; j < 6; j++) {                                               \
                mma_f16(acc[0][j], a0, b[j]);                                           \
                mma_f16(acc[1][j], a1, b[j]);                                           \
            }                                                                           \
        }                                                                               \
    }

    #define ISSUE_B(stageAddr, kt)                                                     \
    {                                                                                   \
        _Pragma("unroll")                                                               \
        for (int i = 0; i < 3; i++)                                                     \
            cp_async16((stageAddr) + (uint32_t)(bRow[i] * (BSTR * 2) + bPart[i] * 16),  \
                       (const char*)g_Bh + (size_t)bRow[i] * (ND * 2)                   \
                           + (size_t)(kt) * (BK * 2) + bPart[i] * 16);                  \
        cp_commit();                                                                    \
    }

    #define STORE_A(faReg, sIdx)                                                       \
    {                                                                                   \
        uint4 o0, o1; cvt16(faReg, o0, o1);                                             \
        __half* dA = &sA[sIdx][aRow * ASTR + aKh];                                      \
        *(uint4*)dA = o0; *(uint4*)(dA + 8) = o1;                                       \
    }

    for (int t = 0; t < NTILES; t += 2) {
        // ---- even sub-iter: compute tile t from sA0/sB0 ----
        if (t + 2 < NTILES) {
            const float* a2 = gA + (t + 2) * BK;
            #pragma unroll
            for (int i = 0; i < 4; i++) fa0[i] = *(const float4*)(a2 + 4 * i);
        }
        ISSUE_B(uB1, t + 1);            // t+1 < NTILES always (t <= NTILES-2)
        COMPUTE_TILE(uA0, &sB[0][0]);
        STORE_A(fa1, 1);                // A(t+1): LDG issued one full iteration ago
        cp_wait0();
        __syncthreads();

        // ---- odd sub-iter: compute tile t+1 from sA1/sB1 ----
        if (t + 3 < NTILES) {
            const float* a2 = gA + (t + 3) * BK;
            #pragma unroll
            for (int i = 0; i < 4; i++) fa1[i] = *(const float4*)(a2 + 4 * i);
        }
        if (t + 2 < NTILES) {
            ISSUE_B(uB0, t + 2);
            COMPUTE_TILE(uA1, &sB[1][0]);
            STORE_A(fa0, 0);            // A(t+2)
            cp_wait0();
            __syncthreads();
        } else {
            COMPUTE_TILE(uA1, &sB[1][0]);   // last tile: nothing to prefetch
        }
    }

    #undef COMPUTE_TILE
    #undef ISSUE_B
    #undef STORE_A

    // ---- epilogue: plain stores; atomicAdd into pre-zeroed label rows ----
    #pragma unroll
    for (int mt = 0; mt < 2; mt++) {
        size_t r0 = (size_t)m0 + wm * 32 + mt * 16 + (lane >> 2);
        size_t r1 = r0 + 8;
        const bool l0 = (tokens[r0] == TOK_LABEL);
        const bool l1 = (tokens[r1] == TOK_LABEL);
        #pragma unroll
        for (int j = 0; j < 6; j++) {
            int c0 = wn * 48 + j * 8 + (lane & 3) * 2;
            float b0 = s_bias[c0], b1 = s_bias[c0 + 1];
            float2 v0 = make_float2(acc[mt][j][0] + b0, acc[mt][j][1] + b1);
            float2 v1 = make_float2(acc[mt][j][2] + b0, acc[mt][j][3] + b1);
            float* p0;
            float* p1;
            if (c0 < N_ACT) {
                p0 = out + r0 * N_ACT + c0;
                p1 = out + r1 * N_ACT + c0;
            } else {
                p0 = out_time + r0 * N_TIME + (c0 - N_ACT);
                p1 = out_time + r1 * N_TIME + (c0 - N_ACT);
            }
            if (l0) { atomicAdd(p0, v0.x); atomicAdd(p0 + 1, v0.y); }
            else    { *(float2*)p0 = v0; }
            if (l1) { atomicAdd(p1, v1.x); atomicAdd(p1 + 1, v1.y); }
            else    { *(float2*)p1 = v1; }
        }
    }
}

// ---------------- launch ----------------
extern "C" void kernel_launch(void* const* d_in, const int* in_sizes, int n_in,
                              void* d_out, int out_size) {
    const int*   tokens = (const int*)  d_in[0];
    const float* h      = (const float*)d_in[1];
    const float* E      = (const float*)d_in[2];
    const float* Wn     = (const float*)d_in[3];
    const float* bn     = (const float*)d_in[4];
    const float* Wt     = (const float*)d_in[5];
    const float* bt     = (const float*)d_in[6];
    const float* tsa    = (const float*)d_in[7];
    const float* tst    = (const float*)d_in[8];
    const float* csa    = (const float*)d_in[9];
    const float* cst    = (const float*)d_in[10];
    const float* cta    = (const float*)d_in[11];
    const float* ctt    = (const float*)d_in[12];
    float* out = (float*)d_out;

    prep_kernel<<<WC_BLOCKS + SCAN_BLOCKS + NORM_BLOCKS, 256>>>(E, Wn, Wt, tsa, tst, tokens, h, out);
    gemm_kernel<<<NSIM + GEMM_TILES, 128>>>(h, out, bn, bt, cta, ctt, csa, cst, tokens);
}

// round 16
// speedup vs baseline: 1.4898x; 1.0346x over previous
#include <cuda_runtime.h>
#include <cuda_fp16.h>
#include <cstdint>

// ---------------- problem constants ----------------
#define TOK_LABEL   2
#define ACT_START   5
#define TIME_START  69
#define NB          8
#define NT_SEQ      2048
#define ND          1024
#define N_ACT       64
#define N_TIME      32
#define N_COLS      96
#define M_TOT       (NB * NT_SEQ)
#define ACT_ELEMS   ((size_t)M_TOT * N_ACT)

// GEMM tiling: 256-thread CTAs, 8 warps, warp tile m32 x n24
#define BM       64
#define BK       32
#define NTILES   (ND / BK)       // 32 (even; loop unrolled by 2)
#define ASTR     40              // smem row stride in halves (80B rows)
#define BSTR     40
#define GEMM_TILES (M_TOT / BM)  // 256
#define SIM_PER_B  5
#define NSIM       (NB * SIM_PER_B)   // 40; grid 296 = 2 x 148 SMs

// ---------------- scratch ----------------
__device__ __align__(16) __half g_Bh[N_COLS * ND];   // folded weights, fp16
__device__ int   g_qlist[NB][NT_SEQ];
__device__ int   g_klist[NB][NT_SEQ];
__device__ int   g_kcls [NB][NT_SEQ];
__device__ int   g_qcnt[NB];
__device__ int   g_kcnt[NB];
__device__ float g_krn[NB][NT_SEQ];                  // 1/||h_k|| indexed by POSITION

// ---------------- helpers ----------------
__device__ __forceinline__ float softplus_f(float x) {
    return (x > 20.0f) ? x : log1pf(expf(x));
}
__device__ __forceinline__ uint32_t smem_u32(const void* p) {
    uint32_t a;
    asm("{ .reg .u64 t; cvta.to.shared.u64 t, %1; cvt.u32.u64 %0, t; }" : "=r"(a) : "l"(p));
    return a;
}
__device__ __forceinline__ void ldsm4(uint32_t* r, uint32_t addr) {
    asm volatile("ldmatrix.sync.aligned.m8n8.x4.shared.b16 {%0,%1,%2,%3}, [%4];"
                 : "=r"(r[0]), "=r"(r[1]), "=r"(r[2]), "=r"(r[3]) : "r"(addr));
}
__device__ __forceinline__ void mma_f16(float* c, const uint32_t* a, const uint32_t* b) {
    asm volatile(
        "mma.sync.aligned.m16n8k16.row.col.f32.f16.f16.f32 "
        "{%0,%1,%2,%3}, {%4,%5,%6,%7}, {%8,%9}, {%0,%1,%2,%3};"
        : "+f"(c[0]), "+f"(c[1]), "+f"(c[2]), "+f"(c[3])
        : "r"(a[0]), "r"(a[1]), "r"(a[2]), "r"(a[3]), "r"(b[0]), "r"(b[1]));
}
__device__ __forceinline__ void cp_async16(uint32_t dst, const void* src) {
    asm volatile("cp.async.ca.shared.global [%0], [%1], 16;" :: "r"(dst), "l"(src));
}
__device__ __forceinline__ void cp_commit() {
    asm volatile("cp.async.commit_group;" ::: "memory");
}
__device__ __forceinline__ void cp_wait0() {
    asm volatile("cp.async.wait_group 0;" ::: "memory");
}
// convert 8 fp32 (2 float4) -> 8 fp16 packed into 1 uint4
__device__ __forceinline__ void cvt8(const float4& f0, const float4& f1, uint4& o) {
    __half2 a = __float22half2_rn(make_float2(f0.x, f0.y));
    __half2 b = __float22half2_rn(make_float2(f0.z, f0.w));
    __half2 c = __float22half2_rn(make_float2(f1.x, f1.y));
    __half2 d = __float22half2_rn(make_float2(f1.z, f1.w));
    o = make_uint4(*(uint32_t*)&a, *(uint32_t*)&b, *(uint32_t*)&c, *(uint32_t*)&d);
}

// ---------------- kernel 1: fold + scan/zero + parallel key norms ----------------
#define WC_BLOCKS   96      // fold: 96 blocks x 1024 elems
#define SCAN_BLOCKS NB      // 8
#define NORM_SEGS   4       // 4 norm blocks per batch (512 positions each)
#define NORM_BLOCKS (NB * NORM_SEGS)

__global__ void prep_kernel(const float* __restrict__ E,
                            const float* __restrict__ Wn,
                            const float* __restrict__ Wt,
                            const float* __restrict__ tsa, const float* __restrict__ tst,
                            const int* __restrict__ tokens,
                            const float* __restrict__ h,
                            float* __restrict__ out) {
    const int tid = threadIdx.x;
    if (blockIdx.x < WC_BLOCKS) {
        int i4 = (blockIdx.x * blockDim.x + tid) * 4;
        float sa = softplus_f(*tsa);
        float st = softplus_f(*tst);
        int r = i4 >> 10;
        int c = i4 & (ND - 1);
        float4 w, e;
        float s;
        if (r < N_ACT) {
            w = *(const float4*)(Wn + r * ND + c);
            e = *(const float4*)(E + (ACT_START + r) * ND + c);
            s = sa;
        } else {
            w = *(const float4*)(Wt + (r - N_ACT) * ND + c);
            e = *(const float4*)(E + (TIME_START + (r - N_ACT)) * ND + c);
            s = st;
        }
        __half2 p0 = __float22half2_rn(make_float2(w.x + s * e.x, w.y + s * e.y));
        __half2 p1 = __float22half2_rn(make_float2(w.z + s * e.z, w.w + s * e.w));
        uint2 o = make_uint2(*(uint32_t*)&p0, *(uint32_t*)&p1);
        *(uint2*)(g_Bh + i4) = o;
        return;
    }
    if (blockIdx.x < WC_BLOCKS + SCAN_BLOCKS) {
        // scan + zero label-query output rows: one block per batch
        const int b   = blockIdx.x - WC_BLOCKS;
        const int* tk = tokens + b * NT_SEQ;
        if (tid == 0) { g_qcnt[b] = 0; g_kcnt[b] = 0; }
        __syncthreads();
        #pragma unroll
        for (int r = 0; r < NT_SEQ / 256; r++) {
            int pos = tid + r * 256;
            int tok = tk[pos];
            if (tok == TOK_LABEL) {
                int s = atomicAdd(&g_qcnt[b], 1);
                g_qlist[b][s] = pos;
            }
            if (pos >= 1 && tok >= ACT_START && tk[pos - 1] == TOK_LABEL) {
                int s = atomicAdd(&g_kcnt[b], 1);
                g_klist[b][s] = pos;
                g_kcls[b][s]  = (tok < TIME_START) ? (tok - ACT_START)
                                                   : (N_ACT + (tok - TIME_START));
            }
        }
        __syncthreads();
        const int qc = g_qcnt[b];
        float* out_time = out + ACT_ELEMS;
        for (int idx = tid; idx < qc * N_COLS; idx += 256) {
            int qi  = idx / N_COLS;
            int col = idx - qi * N_COLS;
            size_t m = (size_t)b * NT_SEQ + g_qlist[b][qi];
            if (col < N_ACT) out[m * N_ACT + col] = 0.0f;
            else             out_time[m * N_TIME + (col - N_ACT)] = 0.0f;
        }
        return;
    }
    // norm blocks: 1/||h_k|| for all key positions, independent of the scan
    const int nb   = blockIdx.x - WC_BLOCKS - SCAN_BLOCKS;
    const int b    = nb >> 2;
    const int seg  = nb & (NORM_SEGS - 1);
    const int warp = tid >> 5;
    const int lane = tid & 31;
    const int* tk  = tokens + b * NT_SEQ;
    const float* hb = h + (size_t)b * NT_SEQ * ND;

    const int base = seg * (NT_SEQ / NORM_SEGS) + warp * 64;   // 8 warps x 64 positions
    #pragma unroll
    for (int ch = 0; ch < 2; ch++) {
        int pos = base + ch * 32 + lane;
        bool hit = (pos >= 1) && (tk[pos] >= ACT_START) && (tk[pos - 1] == TOK_LABEL);
        unsigned mask = __ballot_sync(0xffffffffu, hit);
        while (mask) {
            int bit = __ffs(mask) - 1;
            mask &= mask - 1;
            int kp = base + ch * 32 + bit;
            const float* row = hb + (size_t)kp * ND;
            float s = 0.0f;
            #pragma unroll
            for (int c = 0; c < 8; c++) {
                float4 v = *(const float4*)(row + c * 128 + lane * 4);
                s += v.x*v.x + v.y*v.y + v.z*v.z + v.w*v.w;
            }
            #pragma unroll
            for (int o = 16; o; o >>= 1) s += __shfl_xor_sync(0xffffffffu, s, o);
            if (lane == 0) g_krn[b][kp] = 1.0f / fmaxf(sqrtf(s), 1e-12f);
        }
    }
}

// ---------------- kernel 2: sims (blocks 0..39) + fp16 GEMM (256 thr, m32n24 warps) ----------------
__global__ __launch_bounds__(256, 2)
void gemm_kernel(const float* __restrict__ h, float* __restrict__ out,
                 const float* __restrict__ bn, const float* __restrict__ bt,
                 const float* __restrict__ cta, const float* __restrict__ ctt,
                 const float* __restrict__ csa, const float* __restrict__ cst,
                 const int* __restrict__ tokens) {
    __shared__ __align__(16) __half sA[2][BM * ASTR];       // 2 x 5120 B
    __shared__ __align__(16) __half sB[2][N_COLS * BSTR];   // 2 x 7680 B
    __shared__ float s_bias[N_COLS];

    const int tid  = threadIdx.x;
    const int warp = tid >> 5;
    const int lane = tid & 31;
    float* out_time = out + ACT_ELEMS;

    // ================= sim path (blocks 0..NSIM-1), 8 warps =================
    if (blockIdx.x < NSIM) {
        const int sid   = blockIdx.x;
        const int b     = sid / SIM_PER_B;
        const int qslot = sid - b * SIM_PER_B;
        const int qcnt  = g_qcnt[b];
        if (qslot >= qcnt) return;
        const int kc    = g_kcnt[b];
        const float tau_a = softplus_f(*cta);
        const float tau_t = softplus_f(*ctt);
        const float sca   = softplus_f(*csa);
        const float sct   = softplus_f(*cst);
        const float* hb   = h + (size_t)b * NT_SEQ * ND;
        float* s_acc = s_bias;

        for (int qi = qslot; qi < qcnt; qi += SIM_PER_B) {
            __syncthreads();
            if (tid < N_COLS) s_acc[tid] = 0.0f;
            const int q = g_qlist[b][qi];
            const float* hq = hb + (size_t)q * ND;
            float4 qv[8];
            float nq = 0.0f;
            #pragma unroll
            for (int c = 0; c < 8; c++) {
                qv[c] = *(const float4*)(hq + c * 128 + lane * 4);
                nq += qv[c].x*qv[c].x + qv[c].y*qv[c].y + qv[c].z*qv[c].z + qv[c].w*qv[c].w;
            }
            #pragma unroll
            for (int o = 16; o; o >>= 1) nq += __shfl_xor_sync(0xffffffffu, nq, o);
            const float rnq = 1.0f / fmaxf(sqrtf(nq), 1e-12f);
            __syncthreads();

            // 8 warps, 2 keys per warp per round
            for (int j = warp; j < kc; j += 16) {
                const int jb = j + 8;
                const bool h2 = jb < kc;
                int k1 = g_klist[b][j];
                int k2 = h2 ? g_klist[b][jb] : k1;
                bool m1 = (k1 < q);
                bool m2 = h2 && (k2 < q);
                if (!m1 && !m2) continue;
                const float* p1 = hb + (size_t)k1 * ND;
                const float* p2 = hb + (size_t)k2 * ND;
                float d1 = 0.0f, d2 = 0.0f;
                #pragma unroll
                for (int c = 0; c < 8; c++) {
                    float4 a = *(const float4*)(p1 + c * 128 + lane * 4);
                    float4 v = *(const float4*)(p2 + c * 128 + lane * 4);
                    d1 += qv[c].x*a.x + qv[c].y*a.y + qv[c].z*a.z + qv[c].w*a.w;
                    d2 += qv[c].x*v.x + qv[c].y*v.y + qv[c].z*v.z + qv[c].w*v.w;
                }
                #pragma unroll
                for (int o = 16; o; o >>= 1) {
                    d1 += __shfl_xor_sync(0xffffffffu, d1, o);
                    d2 += __shfl_xor_sync(0xffffffffu, d2, o);
                }
                if (lane == 0) {
                    if (m1) {
                        int cls = g_kcls[b][j];
                        float sim = d1 * rnq * g_krn[b][k1];
                        atomicAdd(&s_acc[cls], sim * (cls < N_ACT ? tau_a : tau_t));
                    }
                    if (m2) {
                        int cls = g_kcls[b][jb];
                        float sim = d2 * rnq * g_krn[b][k2];
                        atomicAdd(&s_acc[cls], sim * (cls < N_ACT ? tau_a : tau_t));
                    }
                }
            }
            __syncthreads();
            const size_t m = (size_t)b * NT_SEQ + q;
            if (tid < N_ACT)
                atomicAdd(&out[m * N_ACT + tid], sca * s_acc[tid]);
            else if (tid < N_COLS)
                atomicAdd(&out_time[m * N_TIME + (tid - N_ACT)], sct * s_acc[tid]);
        }
        return;
    }

    // ================= gemm path: one m-tile per CTA =================
    if (tid < N_COLS) s_bias[tid] = (tid < N_ACT) ? bn[tid] : bt[tid - N_ACT];

    const int wm = warp & 1;       // m-tile of 32
    const int wn = warp >> 1;      // n-tile of 24 (wn = 0..3)
    const int m0 = (blockIdx.x - NSIM) * BM;

    // A load coords: 4 threads per row, 8 floats each (BK=32)
    const int aRow = tid >> 2;
    const int aKh  = (tid & 3) * 8;
    const float* gA = h + (size_t)(m0 + aRow) * ND + aKh;

    const uint32_t uA0 = smem_u32(&sA[0][0]);
    const uint32_t uA1 = smem_u32(&sA[1][0]);
    const uint32_t uB0 = smem_u32(&sB[0][0]);
    const uint32_t uB1 = smem_u32(&sB[1][0]);
    const uint32_t aoff0 = (uint32_t)(((wm * 32 +      (lane & 15)) * ASTR + (lane >> 4) * 8) * 2);
    const uint32_t aoff1 = (uint32_t)(((wm * 32 + 16 + (lane & 15)) * ASTR + (lane >> 4) * 8) * 2);

    // per-thread B cp.async coordinates: 384 16B-chunks over 256 threads
    const int bRow0 = tid >> 2, bPart0 = tid & 3;
    const int c1 = tid + 256;
    const int bRow1 = c1 >> 2, bPart1 = c1 & 3;
    const bool bHas1 = (tid < 128);

    float acc[2][3][4];
    #pragma unroll
    for (int i = 0; i < 2; i++)
        #pragma unroll
        for (int j = 0; j < 3; j++)
            #pragma unroll
            for (int c = 0; c < 4; c++) acc[i][j][c] = 0.0f;

    float4 fa0[2], fa1[2];   // named register sets: A(t) even->fa0, odd->fa1

    #define ISSUE_B(stageAddr, kt)                                                     \
    {                                                                                   \
        cp_async16((stageAddr) + (uint32_t)(bRow0 * (BSTR * 2) + bPart0 * 16),          \
                   (const char*)g_Bh + (size_t)bRow0 * (ND * 2)                         \
                       + (size_t)(kt) * (BK * 2) + bPart0 * 16);                        \
        if (bHas1)                                                                      \
            cp_async16((stageAddr) + (uint32_t)(bRow1 * (BSTR * 2) + bPart1 * 16),      \
                       (const char*)g_Bh + (size_t)bRow1 * (ND * 2)                     \
                           + (size_t)(kt) * (BK * 2) + bPart1 * 16);                    \
        cp_commit();                                                                    \
    }

    #define STORE_A(fr, sIdx)                                                          \
    {                                                                                   \
        uint4 o; cvt8(fr[0], fr[1], o);                                                 \
        *(uint4*)(&sA[sIdx][aRow * ASTR + aKh]) = o;                                    \
    }

    #define COMPUTE_TILE(uA, sb)                                                        \
    {                                                                                   \
        _Pragma("unroll")                                                               \
        for (int ks = 0; ks < 2; ks++) {                                                \
            uint32_t a0[4], a1[4];                                                      \
            ldsm4(a0, (uA) + aoff0 + ks * 32);                                          \
            ldsm4(a1, (uA) + aoff1 + ks * 32);                                          \
            uint32_t b[3][2];                                                           \
            _Pragma("unroll")                                                           \
            for (int j = 0; j < 3; j++) {                                               \
                int n = wn * 24 + j * 8 + (lane >> 2);                                  \
                const __half* p = (sb) + n * BSTR + ks * 16 + (lane & 3) * 2;           \
                b[j][0] = *(const uint32_t*)p;                                          \
                b[j][1] = *(const uint32_t*)(p + 8);                                    \
            }                                                                           \
            _Pragma("unroll")                                                           \
            for (int j = 0; j < 3; j++) {                                               \
                mma_f16(acc[0][j], a0, b[j]);                                           \
                mma_f16(acc[1][j], a1, b[j]);                                           \
            }                                                                           \
        }                                                                               \
    }

    // ---- prologue: issue B(0); LDG A(0),A(1); store A(0)->sA0; wait; sync ----
    ISSUE_B(uB0, 0);
    fa0[0] = *(const float4*)(gA);
    fa0[1] = *(const float4*)(gA + 4);
    fa1[0] = *(const float4*)(gA + BK);
    fa1[1] = *(const float4*)(gA + BK + 4);
    STORE_A(fa0, 0);
    cp_wait0();
    __syncthreads();

    for (int t = 0; t < NTILES; t += 2) {
        // ---- even sub-iter: compute tile t from sA0/sB0 ----
        if (t + 2 < NTILES) {
            const float* a2 = gA + (t + 2) * BK;
            fa0[0] = *(const float4*)(a2);
            fa0[1] = *(const float4*)(a2 + 4);
        }
        ISSUE_B(uB1, t + 1);
        COMPUTE_TILE(uA0, &sB[0][0]);
        STORE_A(fa1, 1);                // A(t+1): LDG issued one full iteration ago
        cp_wait0();
        __syncthreads();

        // ---- odd sub-iter: compute tile t+1 from sA1/sB1 ----
        if (t + 3 < NTILES) {
            const float* a2 = gA + (t + 3) * BK;
            fa1[0] = *(const float4*)(a2);
            fa1[1] = *(const float4*)(a2 + 4);
        }
        if (t + 2 < NTILES) {
            ISSUE_B(uB0, t + 2);
            COMPUTE_TILE(uA1, &sB[1][0]);
            STORE_A(fa0, 0);            // A(t+2)
            cp_wait0();
            __syncthreads();
        } else {
            COMPUTE_TILE(uA1, &sB[1][0]);   // last tile: nothing to prefetch
        }
    }

    #undef COMPUTE_TILE
    #undef ISSUE_B
    #undef STORE_A

    // ---- epilogue: plain stores; atomicAdd into pre-zeroed label rows ----
    #pragma unroll
    for (int mt = 0; mt < 2; mt++) {
        size_t r0 = (size_t)m0 + wm * 32 + mt * 16 + (lane >> 2);
        size_t r1 = r0 + 8;
        const bool l0 = (tokens[r0] == TOK_LABEL);
        const bool l1 = (tokens[r1] == TOK_LABEL);
        #pragma unroll
        for (int j = 0; j < 3; j++) {
            int c0 = wn * 24 + j * 8 + (lane & 3) * 2;
            float b0 = s_bias[c0], b1 = s_bias[c0 + 1];
            float2 v0 = make_float2(acc[mt][j][0] + b0, acc[mt][j][1] + b1);
            float2 v1 = make_float2(acc[mt][j][2] + b0, acc[mt][j][3] + b1);
            float* p0;
            float* p1;
            if (c0 < N_ACT) {
                p0 = out + r0 * N_ACT + c0;
                p1 = out + r1 * N_ACT + c0;
            } else {
                p0 = out_time + r0 * N_TIME + (c0 - N_ACT);
                p1 = out_time + r1 * N_TIME + (c0 - N_ACT);
            }
            if (l0) { atomicAdd(p0, v0.x); atomicAdd(p0 + 1, v0.y); }
            else    { *(float2*)p0 = v0; }
            if (l1) { atomicAdd(p1, v1.x); atomicAdd(p1 + 1, v1.y); }
            else    { *(float2*)p1 = v1; }
        }
    }
}

// ---------------- launch ----------------
extern "C" void kernel_launch(void* const* d_in, const int* in_sizes, int n_in,
                              void* d_out, int out_size) {
    const int*   tokens = (const int*)  d_in[0];
    const float* h      = (const float*)d_in[1];
    const float* E      = (const float*)d_in[2];
    const float* Wn     = (const float*)d_in[3];
    const float* bn     = (const float*)d_in[4];
    const float* Wt     = (const float*)d_in[5];
    const float* bt     = (const float*)d_in[6];
    const float* tsa    = (const float*)d_in[7];
    const float* tst    = (const float*)d_in[8];
    const float* csa    = (const float*)d_in[9];
    const float* cst    = (const float*)d_in[10];
    const float* cta    = (const float*)d_in[11];
    const float* ctt    = (const float*)d_in[12];
    float* out = (float*)d_out;

    prep_kernel<<<WC_BLOCKS + SCAN_BLOCKS + NORM_BLOCKS, 256>>>(E, Wn, Wt, tsa, tst, tokens, h, out);
    gemm_kernel<<<NSIM + GEMM_TILES, 256>>>(h, out, bn, bt, cta, ctt, csa, cst, tokens);
}

// round 17
// speedup vs baseline: 1.5113x; 1.0144x over previous
#include <cuda_runtime.h>
#include <cuda_fp16.h>
#include <cstdint>

// ---------------- problem constants ----------------
#define TOK_LABEL   2
#define ACT_START   5
#define TIME_START  69
#define NB          8
#define NT_SEQ      2048
#define ND          1024
#define N_ACT       64
#define N_TIME      32
#define N_COLS      96
#define M_TOT       (NB * NT_SEQ)
#define ACT_ELEMS   ((size_t)M_TOT * N_ACT)

// GEMM tiling: 256-thread CTAs, 8 warps, warp tile m32 x n24
#define BM       64
#define BK       32
#define NTILES   (ND / BK)       // 32 (even; loop unrolled by 2)
#define ASTR     40              // smem row stride in halves (80B rows)
#define BSTR     40
#define GEMM_TILES (M_TOT / BM)  // 256
#define SIM_PER_B  5
#define NSIM       (NB * SIM_PER_B)   // 40; grid 296 = 2 x 148 SMs

// ---------------- scratch ----------------
__device__ __align__(16) __half g_Bh[N_COLS * ND];   // folded weights, fp16
__device__ int   g_qlist[NB][NT_SEQ];
__device__ int   g_klist[NB][NT_SEQ];
__device__ int   g_kcls [NB][NT_SEQ];
__device__ int   g_qcnt[NB];
__device__ int   g_kcnt[NB];
__device__ float g_krn[NB][NT_SEQ];                  // 1/||h_k|| indexed by POSITION

// ---------------- helpers ----------------
__device__ __forceinline__ float softplus_f(float x) {
    return (x > 20.0f) ? x : log1pf(expf(x));
}
__device__ __forceinline__ uint32_t smem_u32(const void* p) {
    uint32_t a;
    asm("{ .reg .u64 t; cvta.to.shared.u64 t, %1; cvt.u32.u64 %0, t; }" : "=r"(a) : "l"(p));
    return a;
}
__device__ __forceinline__ void ldsm4(uint32_t* r, uint32_t addr) {
    asm volatile("ldmatrix.sync.aligned.m8n8.x4.shared.b16 {%0,%1,%2,%3}, [%4];"
                 : "=r"(r[0]), "=r"(r[1]), "=r"(r[2]), "=r"(r[3]) : "r"(addr));
}
__device__ __forceinline__ uint32_t lds32(uint32_t addr) {
    uint32_t v;
    asm volatile("ld.shared.b32 %0, [%1];" : "=r"(v) : "r"(addr));
    return v;
}
__device__ __forceinline__ void mma_f16(float* c, const uint32_t* a, const uint32_t* b) {
    asm volatile(
        "mma.sync.aligned.m16n8k16.row.col.f32.f16.f16.f32 "
        "{%0,%1,%2,%3}, {%4,%5,%6,%7}, {%8,%9}, {%0,%1,%2,%3};"
        : "+f"(c[0]), "+f"(c[1]), "+f"(c[2]), "+f"(c[3])
        : "r"(a[0]), "r"(a[1]), "r"(a[2]), "r"(a[3]), "r"(b[0]), "r"(b[1]));
}
__device__ __forceinline__ void cp_async16(uint32_t dst, const void* src) {
    asm volatile("cp.async.ca.shared.global [%0], [%1], 16;" :: "r"(dst), "l"(src));
}
__device__ __forceinline__ void cp_commit() {
    asm volatile("cp.async.commit_group;" ::: "memory");
}
__device__ __forceinline__ void cp_wait0() {
    asm volatile("cp.async.wait_group 0;" ::: "memory");
}
__device__ __forceinline__ void cp_wait1() {
    asm volatile("cp.async.wait_group 1;" ::: "memory");
}
// convert 8 fp32 (2 float4) -> 8 fp16 packed into 1 uint4
__device__ __forceinline__ void cvt8(const float4& f0, const float4& f1, uint4& o) {
    __half2 a = __float22half2_rn(make_float2(f0.x, f0.y));
    __half2 b = __float22half2_rn(make_float2(f0.z, f0.w));
    __half2 c = __float22half2_rn(make_float2(f1.x, f1.y));
    __half2 d = __float22half2_rn(make_float2(f1.z, f1.w));
    o = make_uint4(*(uint32_t*)&a, *(uint32_t*)&b, *(uint32_t*)&c, *(uint32_t*)&d);
}

// ---------------- kernel 1: fold + scan/zero + parallel key norms ----------------
#define WC_BLOCKS   96      // fold: 96 blocks x 1024 elems
#define SCAN_BLOCKS NB      // 8
#define NORM_SEGS   4       // 4 norm blocks per batch (512 positions each)
#define NORM_BLOCKS (NB * NORM_SEGS)

__global__ void prep_kernel(const float* __restrict__ E,
                            const float* __restrict__ Wn,
                            const float* __restrict__ Wt,
                            const float* __restrict__ tsa, const float* __restrict__ tst,
                            const int* __restrict__ tokens,
                            const float* __restrict__ h,
                            float* __restrict__ out) {
    const int tid = threadIdx.x;
    if (blockIdx.x < WC_BLOCKS) {
        int i4 = (blockIdx.x * blockDim.x + tid) * 4;
        float sa = softplus_f(*tsa);
        float st = softplus_f(*tst);
        int r = i4 >> 10;
        int c = i4 & (ND - 1);
        float4 w, e;
        float s;
        if (r < N_ACT) {
            w = *(const float4*)(Wn + r * ND + c);
            e = *(const float4*)(E + (ACT_START + r) * ND + c);
            s = sa;
        } else {
            w = *(const float4*)(Wt + (r - N_ACT) * ND + c);
            e = *(const float4*)(E + (TIME_START + (r - N_ACT)) * ND + c);
            s = st;
        }
        __half2 p0 = __float22half2_rn(make_float2(w.x + s * e.x, w.y + s * e.y));
        __half2 p1 = __float22half2_rn(make_float2(w.z + s * e.z, w.w + s * e.w));
        uint2 o = make_uint2(*(uint32_t*)&p0, *(uint32_t*)&p1);
        *(uint2*)(g_Bh + i4) = o;
        return;
    }
    if (blockIdx.x < WC_BLOCKS + SCAN_BLOCKS) {
        // scan + zero label-query output rows: one block per batch
        const int b   = blockIdx.x - WC_BLOCKS;
        const int* tk = tokens + b * NT_SEQ;
        if (tid == 0) { g_qcnt[b] = 0; g_kcnt[b] = 0; }
        __syncthreads();
        #pragma unroll
        for (int r = 0; r < NT_SEQ / 256; r++) {
            int pos = tid + r * 256;
            int tok = tk[pos];
            if (tok == TOK_LABEL) {
                int s = atomicAdd(&g_qcnt[b], 1);
                g_qlist[b][s] = pos;
            }
            if (pos >= 1 && tok >= ACT_START && tk[pos - 1] == TOK_LABEL) {
                int s = atomicAdd(&g_kcnt[b], 1);
                g_klist[b][s] = pos;
                g_kcls[b][s]  = (tok < TIME_START) ? (tok - ACT_START)
                                                   : (N_ACT + (tok - TIME_START));
            }
        }
        __syncthreads();
        const int qc = g_qcnt[b];
        float* out_time = out + ACT_ELEMS;
        for (int idx = tid; idx < qc * N_COLS; idx += 256) {
            int qi  = idx / N_COLS;
            int col = idx - qi * N_COLS;
            size_t m = (size_t)b * NT_SEQ + g_qlist[b][qi];
            if (col < N_ACT) out[m * N_ACT + col] = 0.0f;
            else             out_time[m * N_TIME + (col - N_ACT)] = 0.0f;
        }
        return;
    }
    // norm blocks: 1/||h_k|| for all key positions, independent of the scan
    const int nb   = blockIdx.x - WC_BLOCKS - SCAN_BLOCKS;
    const int b    = nb >> 2;
    const int seg  = nb & (NORM_SEGS - 1);
    const int warp = tid >> 5;
    const int lane = tid & 31;
    const int* tk  = tokens + b * NT_SEQ;
    const float* hb = h + (size_t)b * NT_SEQ * ND;

    const int base = seg * (NT_SEQ / NORM_SEGS) + warp * 64;   // 8 warps x 64 positions
    #pragma unroll
    for (int ch = 0; ch < 2; ch++) {
        int pos = base + ch * 32 + lane;
        bool hit = (pos >= 1) && (tk[pos] >= ACT_START) && (tk[pos - 1] == TOK_LABEL);
        unsigned mask = __ballot_sync(0xffffffffu, hit);
        while (mask) {
            int bit = __ffs(mask) - 1;
            mask &= mask - 1;
            int kp = base + ch * 32 + bit;
            const float* row = hb + (size_t)kp * ND;
            float s = 0.0f;
            #pragma unroll
            for (int c = 0; c < 8; c++) {
                float4 v = *(const float4*)(row + c * 128 + lane * 4);
                s += v.x*v.x + v.y*v.y + v.z*v.z + v.w*v.w;
            }
            #pragma unroll
            for (int o = 16; o; o >>= 1) s += __shfl_xor_sync(0xffffffffu, s, o);
            if (lane == 0) g_krn[b][kp] = 1.0f / fmaxf(sqrtf(s), 1e-12f);
        }
    }
}

// ---------------- kernel 2: sims (blocks 0..39) + fp16 GEMM (3-stage B ring) ----------------
__global__ __launch_bounds__(256, 2)
void gemm_kernel(const float* __restrict__ h, float* __restrict__ out,
                 const float* __restrict__ bn, const float* __restrict__ bt,
                 const float* __restrict__ cta, const float* __restrict__ ctt,
                 const float* __restrict__ csa, const float* __restrict__ cst,
                 const int* __restrict__ tokens) {
    __shared__ __align__(16) __half sA[2][BM * ASTR];       // 2 x 5120 B
    __shared__ __align__(16) __half sB[3][N_COLS * BSTR];   // 3 x 7680 B
    __shared__ float s_bias[N_COLS];

    const int tid  = threadIdx.x;
    const int warp = tid >> 5;
    const int lane = tid & 31;
    float* out_time = out + ACT_ELEMS;

    // ================= sim path (blocks 0..NSIM-1), 8 warps =================
    if (blockIdx.x < NSIM) {
        const int sid   = blockIdx.x;
        const int b     = sid / SIM_PER_B;
        const int qslot = sid - b * SIM_PER_B;
        const int qcnt  = g_qcnt[b];
        if (qslot >= qcnt) return;
        const int kc    = g_kcnt[b];
        const float tau_a = softplus_f(*cta);
        const float tau_t = softplus_f(*ctt);
        const float sca   = softplus_f(*csa);
        const float sct   = softplus_f(*cst);
        const float* hb   = h + (size_t)b * NT_SEQ * ND;
        float* s_acc = s_bias;

        for (int qi = qslot; qi < qcnt; qi += SIM_PER_B) {
            __syncthreads();
            if (tid < N_COLS) s_acc[tid] = 0.0f;
            const int q = g_qlist[b][qi];
            const float* hq = hb + (size_t)q * ND;
            float4 qv[8];
            float nq = 0.0f;
            #pragma unroll
            for (int c = 0; c < 8; c++) {
                qv[c] = *(const float4*)(hq + c * 128 + lane * 4);
                nq += qv[c].x*qv[c].x + qv[c].y*qv[c].y + qv[c].z*qv[c].z + qv[c].w*qv[c].w;
            }
            #pragma unroll
            for (int o = 16; o; o >>= 1) nq += __shfl_xor_sync(0xffffffffu, nq, o);
            const float rnq = 1.0f / fmaxf(sqrtf(nq), 1e-12f);
            __syncthreads();

            // 8 warps, 2 keys per warp per round
            for (int j = warp; j < kc; j += 16) {
                const int jb = j + 8;
                const bool h2 = jb < kc;
                int k1 = g_klist[b][j];
                int k2 = h2 ? g_klist[b][jb] : k1;
                bool m1 = (k1 < q);
                bool m2 = h2 && (k2 < q);
                if (!m1 && !m2) continue;
                const float* p1 = hb + (size_t)k1 * ND;
                const float* p2 = hb + (size_t)k2 * ND;
                float d1 = 0.0f, d2 = 0.0f;
                #pragma unroll
                for (int c = 0; c < 8; c++) {
                    float4 a = *(const float4*)(p1 + c * 128 + lane * 4);
                    float4 v = *(const float4*)(p2 + c * 128 + lane * 4);
                    d1 += qv[c].x*a.x + qv[c].y*a.y + qv[c].z*a.z + qv[c].w*a.w;
                    d2 += qv[c].x*v.x + qv[c].y*v.y + qv[c].z*v.z + qv[c].w*v.w;
                }
                #pragma unroll
                for (int o = 16; o; o >>= 1) {
                    d1 += __shfl_xor_sync(0xffffffffu, d1, o);
                    d2 += __shfl_xor_sync(0xffffffffu, d2, o);
                }
                if (lane == 0) {
                    if (m1) {
                        int cls = g_kcls[b][j];
                        float sim = d1 * rnq * g_krn[b][k1];
                        atomicAdd(&s_acc[cls], sim * (cls < N_ACT ? tau_a : tau_t));
                    }
                    if (m2) {
                        int cls = g_kcls[b][jb];
                        float sim = d2 * rnq * g_krn[b][k2];
                        atomicAdd(&s_acc[cls], sim * (cls < N_ACT ? tau_a : tau_t));
                    }
                }
            }
            __syncthreads();
            const size_t m = (size_t)b * NT_SEQ + q;
            if (tid < N_ACT)
                atomicAdd(&out[m * N_ACT + tid], sca * s_acc[tid]);
            else if (tid < N_COLS)
                atomicAdd(&out_time[m * N_TIME + (tid - N_ACT)], sct * s_acc[tid]);
        }
        return;
    }

    // ================= gemm path: one m-tile per CTA =================
    if (tid < N_COLS) s_bias[tid] = (tid < N_ACT) ? bn[tid] : bt[tid - N_ACT];

    const int wm = warp & 1;       // m-tile of 32
    const int wn = warp >> 1;      // n-tile of 24 (wn = 0..3)
    const int m0 = (blockIdx.x - NSIM) * BM;

    // A load coords: 4 threads per row, 8 floats each (BK=32)
    const int aRow = tid >> 2;
    const int aKh  = (tid & 3) * 8;
    const float* gA = h + (size_t)(m0 + aRow) * ND + aKh;

    const uint32_t uA0 = smem_u32(&sA[0][0]);
    const uint32_t uA1 = smem_u32(&sA[1][0]);
    const uint32_t aoff0 = (uint32_t)(((wm * 32 +      (lane & 15)) * ASTR + (lane >> 4) * 8) * 2);
    const uint32_t aoff1 = (uint32_t)(((wm * 32 + 16 + (lane & 15)) * ASTR + (lane >> 4) * 8) * 2);
    // B fragment base offset (bytes within a stage) for this thread
    const uint32_t boffBase = (uint32_t)(((wn * 24 + (lane >> 2)) * BSTR + (lane & 3) * 2) * 2);

    // rotating B-stage base addresses (plain register rotation, no indexing)
    uint32_t b_cur = smem_u32(&sB[0][0]);
    uint32_t b_nxt = smem_u32(&sB[1][0]);
    uint32_t b_nn  = smem_u32(&sB[2][0]);

    // per-thread B cp.async coordinates: 384 16B-chunks over 256 threads
    const int bRow0 = tid >> 2, bPart0 = tid & 3;
    const int c1 = tid + 256;
    const int bRow1 = c1 >> 2, bPart1 = c1 & 3;
    const bool bHas1 = (tid < 128);

    float acc[2][3][4];
    #pragma unroll
    for (int i = 0; i < 2; i++)
        #pragma unroll
        for (int j = 0; j < 3; j++)
            #pragma unroll
            for (int c = 0; c < 4; c++) acc[i][j][c] = 0.0f;

    float4 fa0[2], fa1[2];   // named register sets: A(t) even->fa0, odd->fa1

    #define ISSUE_B(stageAddr, kt)                                                     \
    {                                                                                   \
        cp_async16((stageAddr) + (uint32_t)(bRow0 * (BSTR * 2) + bPart0 * 16),          \
                   (const char*)g_Bh + (size_t)bRow0 * (ND * 2)                         \
                       + (size_t)(kt) * (BK * 2) + bPart0 * 16);                        \
        if (bHas1)                                                                      \
            cp_async16((stageAddr) + (uint32_t)(bRow1 * (BSTR * 2) + bPart1 * 16),      \
                       (const char*)g_Bh + (size_t)bRow1 * (ND * 2)                     \
                           + (size_t)(kt) * (BK * 2) + bPart1 * 16);                    \
        cp_commit();                                                                    \
    }

    #define STORE_A(fr, sIdx)                                                          \
    {                                                                                   \
        uint4 o; cvt8(fr[0], fr[1], o);                                                 \
        *(uint4*)(&sA[sIdx][aRow * ASTR + aKh]) = o;                                    \
    }

    #define COMPUTE_TILE(uA, uBb)                                                       \
    {                                                                                   \
        _Pragma("unroll")                                                               \
        for (int ks = 0; ks < 2; ks++) {                                                \
            uint32_t a0[4], a1[4];                                                      \
            ldsm4(a0, (uA) + aoff0 + ks * 32);                                          \
            ldsm4(a1, (uA) + aoff1 + ks * 32);                                          \
            uint32_t b[3][2];                                                           \
            _Pragma("unroll")                                                           \
            for (int j = 0; j < 3; j++) {                                               \
                uint32_t e = (uBb) + boffBase + (uint32_t)(j * 8 * BSTR * 2 + ks * 32); \
                b[j][0] = lds32(e);                                                     \
                b[j][1] = lds32(e + 16);                                                \
            }                                                                           \
            _Pragma("unroll")                                                           \
            for (int j = 0; j < 3; j++) {                                               \
                mma_f16(acc[0][j], a0, b[j]);                                           \
                mma_f16(acc[1][j], a1, b[j]);                                           \
            }                                                                           \
        }                                                                               \
    }

    #define ROTATE_B() { uint32_t _t = b_cur; b_cur = b_nxt; b_nxt = b_nn; b_nn = _t; }

    // ---- prologue: issue B(0),B(1); LDG A(0),A(1); store A(0)->sA0; wait1; sync ----
    ISSUE_B(b_cur, 0);
    ISSUE_B(b_nxt, 1);
    fa0[0] = *(const float4*)(gA);
    fa0[1] = *(const float4*)(gA + 4);
    fa1[0] = *(const float4*)(gA + BK);
    fa1[1] = *(const float4*)(gA + BK + 4);
    STORE_A(fa0, 0);
    cp_wait1();          // B(0) landed; B(1) may still fly
    __syncthreads();

    for (int t = 0; t < NTILES; t += 2) {
        // ---- even sub-iter: compute tile t from sA0 / b_cur ----
        if (t + 2 < NTILES) {
            const float* a2 = gA + (t + 2) * BK;
            fa0[0] = *(const float4*)(a2);
            fa0[1] = *(const float4*)(a2 + 4);
            ISSUE_B(b_nn, t + 2);
        }
        COMPUTE_TILE(uA0, b_cur);
        STORE_A(fa1, 1);                 // A(t+1): LDG issued one full iteration ago
        if (t + 2 < NTILES) cp_wait1();  // B(t+1) landed (issued last iteration)
        else                cp_wait0();
        __syncthreads();
        ROTATE_B();

        // ---- odd sub-iter: compute tile t+1 from sA1 / b_cur ----
        if (t + 3 < NTILES) {
            const float* a2 = gA + (t + 3) * BK;
            fa1[0] = *(const float4*)(a2);
            fa1[1] = *(const float4*)(a2 + 4);
            ISSUE_B(b_nn, t + 3);
        }
        COMPUTE_TILE(uA1, b_cur);
        if (t + 2 < NTILES) {
            STORE_A(fa0, 0);             // A(t+2)
            if (t + 3 < NTILES) cp_wait1();
            else                cp_wait0();
            __syncthreads();
            ROTATE_B();
        }
    }

    #undef COMPUTE_TILE
    #undef ISSUE_B
    #undef STORE_A
    #undef ROTATE_B

    // ---- epilogue: plain stores; atomicAdd into pre-zeroed label rows ----
    #pragma unroll
    for (int mt = 0; mt < 2; mt++) {
        size_t r0 = (size_t)m0 + wm * 32 + mt * 16 + (lane >> 2);
        size_t r1 = r0 + 8;
        const bool l0 = (tokens[r0] == TOK_LABEL);
        const bool l1 = (tokens[r1] == TOK_LABEL);
        #pragma unroll
        for (int j = 0; j < 3; j++) {
            int c0 = wn * 24 + j * 8 + (lane & 3) * 2;
            float b0 = s_bias[c0], b1 = s_bias[c0 + 1];
            float2 v0 = make_float2(acc[mt][j][0] + b0, acc[mt][j][1] + b1);
            float2 v1 = make_float2(acc[mt][j][2] + b0, acc[mt][j][3] + b1);
            float* p0;
            float* p1;
            if (c0 < N_ACT) {
                p0 = out + r0 * N_ACT + c0;
                p1 = out + r1 * N_ACT + c0;
            } else {
                p0 = out_time + r0 * N_TIME + (c0 - N_ACT);
                p1 = out_time + r1 * N_TIME + (c0 - N_ACT);
            }
            if (l0) { atomicAdd(p0, v0.x); atomicAdd(p0 + 1, v0.y); }
            else    { *(float2*)p0 = v0; }
            if (l1) { atomicAdd(p1, v1.x); atomicAdd(p1 + 1, v1.y); }
            else    { *(float2*)p1 = v1; }
        }
    }
}

// ---------------- launch ----------------
extern "C" void kernel_launch(void* const* d_in, const int* in_sizes, int n_in,
                              void* d_out, int out_size) {
    const int*   tokens = (const int*)  d_in[0];
    const float* h      = (const float*)d_in[1];
    const float* E      = (const float*)d_in[2];
    const float* Wn     = (const float*)d_in[3];
    const float* bn     = (const float*)d_in[4];
    const float* Wt     = (const float*)d_in[5];
    const float* bt     = (const float*)d_in[6];
    const float* tsa    = (const float*)d_in[7];
    const float* tst    = (const float*)d_in[8];
    const float* csa    = (const float*)d_in[9];
    const float* cst    = (const float*)d_in[10];
    const float* cta    = (const float*)d_in[11];
    const float* ctt    = (const float*)d_in[12];
    float* out = (float*)d_out;

    prep_kernel<<<WC_BLOCKS + SCAN_BLOCKS + NORM_BLOCKS, 256>>>(E, Wn, Wt, tsa, tst, tokens, h, out);
    gemm_kernel<<<NSIM + GEMM_TILES, 256>>>(h, out, bn, bt, cta, ctt, csa, cst, tokens);
}